// round 12
// baseline (speedup 1.0000x reference)
#include <cuda_runtime.h>
#include <math.h>
#include <stdint.h>

// ---------------- problem constants ----------------
#define cL    64
#define cEMB  128
#define cH2   128
#define cG3   384      /* 3*H2 */
#define cEXC  256
#define cHID  256
#define cN    200000
#define cK    10

#define OUT_PRED 0L
#define OUT_EXCS 1L
#define OUT_HS   (1L + (long)(cN + 1) * cEXC)   /* 51200257 */

#define NBLK  148                 /* 2 GRU + 146 workers, exactly 1 wave */
#define NWRK  146
#define TPB   1024
#define NCAND 1460
#define FULLM 0xffffffffu

#define QHS   ((long)cN * cHID / 4 - 1)   /* 12,799,999 shifted f4 slots */
#define SHS_TOT (12800000L)               /* total f4 in hs */
#define NG1   3125                /* phase-1 granules of 4096 f4 (64KB) */
#define NG2   6250                /* phase-2 granules of 32 rows (32KB) */
#define NDL   16                  /* max deferred granules per block */

// smem layout (floats):
//   GRU blocks:   [0,49152) W | [49152,49408) hbuf | [49408,49792) gsh
//                 | [49792,49920) gin
//   worker blocks:[0,32800) staging (p1: 2x16400, p2: 2x8192) | wv/wis/xs
#define SM_FLOATS 51200
#define BUFSTRIDE 16400           /* p1 staging floats (4097 f4 + pad) */
#define B2STRIDE  8192            /* p2 staging floats (32 rows x 256) */
#define WV_OFF 49920
#define WI_OFF 50240
#define XS_OFF 50560

// ---------------- device scratch (no allocs allowed) ----------------
__device__ float g_gi[2][cL][cG3];
__device__ float g_exc[cEXC];
__device__ float g_cv[NCAND];
__device__ int   g_ci[NCAND];
__device__ float g_giv[3 * cHID];
__device__ float g_ghv[3 * cHID];
__device__ int   g_gi_done;
__device__ int   g_gru_done;
__device__ int   g_ticket;

__device__ __forceinline__ float sigmoidf_(float x) {
    return 1.0f / (1.0f + expf(-x));
}

#define BAR384() asm volatile("bar.sync 1, 384;" ::: "memory")
#define CPA16(saddr, gptr) \
    asm volatile("cp.async.cg.shared.global [%0], [%1], 16;" \
                 :: "r"(saddr), "l"(gptr))
#define CPA_COMMIT() asm volatile("cp.async.commit_group;" ::: "memory")
#define CPA_WAIT1()  asm volatile("cp.async.wait_group 1;" ::: "memory")
#define CPA_WAIT0()  asm volatile("cp.async.wait_group 0;" ::: "memory")

__device__ __forceinline__ void fma_x2(unsigned long long& acc, double w, double h) {
    asm("fma.rn.f32x2 %0, %1, %2, %0;"
        : "+l"(acc)
        : "l"(__double_as_longlong(w)), "l"(__double_as_longlong(h)));
}
__device__ __forceinline__ void unpack_x2(unsigned long long v, float& lo, float& hi) {
    asm("mov.b64 {%0, %1}, %2;" : "=f"(lo), "=f"(hi) : "l"(v));
}

// ============================================================
__global__ void __launch_bounds__(TPB, 1)
fused_kernel(const int* __restrict__ exec_ids,
             const float* __restrict__ emb,
             const float* __restrict__ score,
             const float* __restrict__ excs,
             const float* __restrict__ hs,
             const float* __restrict__ wf_Wih, const float* __restrict__ wf_bih,
             const float* __restrict__ wb_Wih, const float* __restrict__ wb_bih,
             const float* __restrict__ wf_Whh, const float* __restrict__ wf_bhh,
             const float* __restrict__ wb_Whh, const float* __restrict__ wb_bhh,
             const float* __restrict__ s_Wih,  const float* __restrict__ s_Whh,
             const float* __restrict__ s_bih,  const float* __restrict__ s_bhh,
             const float* __restrict__ out_W,  const float* __restrict__ out_b,
             float* __restrict__ out) {
    extern __shared__ float sm[];
    __shared__ int is_last;
    __shared__ int sh_ready;
    int t = threadIdx.x;
    int lane = t & 31;
    int warp = t >> 5;
    int b = blockIdx.x;

    if (b < 2) {
        // ================= GRU block (dir = b) =================
        if (warp < 12) {
            int dir = b;
            float* Wsh  = sm;
            float* hbuf = sm + cG3 * cH2;
            float* gsh  = hbuf + 256;
            float* gin  = gsh + 384;

            const float* Whh = dir ? wb_Whh : wf_Whh;
            const float* bhh = dir ? wb_bhh : wf_bhh;

            for (int idx = t; idx < cG3 * cH2 / 4; idx += 384) {
                int kk = idx / cG3;
                int tt = idx - kk * cG3;
                ((float4*)Wsh)[idx] = *(const float4*)(Whh + (long)tt * cH2 + kk * 4);
            }
            if (t < cH2) hbuf[t] = 0.0f;
            float bhh_t = bhh[t];
            float hmax = -1e30f;

            if (t == 0) {
                while (*(volatile int*)&g_gi_done < 128) __nanosleep(32);
            }
            BAR384();
            __threadfence();

            float gi_cur = g_gi[dir][0][t];
            const double2* W2 = ((const double2*)Wsh) + t;

            for (int s = 0; s < cL; ++s) {
                float gi_nxt = (s + 1 < cL) ? g_gi[dir][s + 1][t] : 0.0f;
                float* hcur = hbuf + ((s & 1) ? 128 : 0);
                float* hnxt = hbuf + ((s & 1) ? 0 : 128);
                const double2* H2 = (const double2*)hcur;

                unsigned long long aA = 0, aB = 0, aC = 0, aD = 0;
#pragma unroll
                for (int kk = 0; kk < 32; kk += 2) {
                    double2 w0 = W2[(long)kk * cG3];
                    double2 h0 = H2[kk];
                    double2 w1 = W2[(long)(kk + 1) * cG3];
                    double2 h1 = H2[kk + 1];
                    fma_x2(aA, w0.x, h0.x);
                    fma_x2(aB, w0.y, h0.y);
                    fma_x2(aC, w1.x, h1.x);
                    fma_x2(aD, w1.y, h1.y);
                }
                float p0, p1, p2, p3, p4, p5, p6, p7;
                unpack_x2(aA, p0, p1);
                unpack_x2(aB, p2, p3);
                unpack_x2(aC, p4, p5);
                unpack_x2(aD, p6, p7);
                float gh = ((p0 + p1) + (p2 + p3)) + ((p4 + p5) + (p6 + p7)) + bhh_t;

                if (t < 256) {
                    gsh[t] = sigmoidf_(gi_cur + gh);
                } else {
                    gsh[t] = gh;
                    gin[t - 256] = gi_cur;
                }
                BAR384();

                if (t < cH2) {
                    float r = gsh[t];
                    float z = gsh[128 + t];
                    float n = tanhf(gin[t] + r * gsh[256 + t]);
                    float hn = (1.0f - z) * n + z * hcur[t];
                    hnxt[t] = hn;
                    hmax = fmaxf(hmax, hn);
                }
                BAR384();
                gi_cur = gi_nxt;
            }
            if (t < cH2) g_exc[dir * cH2 + t] = hmax;
            __threadfence();
            BAR384();
            if (t == 0) atomicAdd(&g_gru_done, 1);

            if (t == 0) {
                while (*(volatile int*)&g_gru_done < 2) __nanosleep(64);
            }
            BAR384();
            __threadfence();

            // ---- seq-GRU gate preacts: 12 warps x 32 gates ----
            const float4* exc4 = (const float4*)g_exc;
            const float4* hr4  = (const float4*)(hs + (long)(cN - 1) * cHID);
            float4 xa = exc4[lane], xb = exc4[32 + lane];
            float4 ha = hr4[lane],  hb = hr4[32 + lane];
            int off = (score[0] >= 0.5f) ? 0 : 256;
#pragma unroll 4
            for (int jj = 0; jj < 32; ++jj) {
                int g = b * 384 + warp * 32 + jj;
                const float4* wi4 = (const float4*)(s_Wih + (long)g * 512 + off);
                const float4* wh4 = (const float4*)(s_Whh + (long)g * 256);
                float4 a = wi4[lane], bb = wi4[lane + 32];
                float4 c = wh4[lane], d = wh4[lane + 32];
                float giv = a.x * xa.x + a.y * xa.y + a.z * xa.z + a.w * xa.w
                          + bb.x * xb.x + bb.y * xb.y + bb.z * xb.z + bb.w * xb.w;
                float ghv = c.x * ha.x + c.y * ha.y + c.z * ha.z + c.w * ha.w
                          + d.x * hb.x + d.y * hb.y + d.z * hb.z + d.w * hb.w;
#pragma unroll
                for (int o = 16; o; o >>= 1) {
                    giv += __shfl_xor_sync(FULLM, giv, o);
                    ghv += __shfl_xor_sync(FULLM, ghv, o);
                }
                if (lane == 0) {
                    g_giv[g] = giv + s_bih[g];
                    g_ghv[g] = ghv + s_bhh[g];
                }
            }
            __threadfence();
        }
        __syncthreads();
    } else {
        // ================= worker block =================
        int wb = b - 2;
        float* wv  = sm + WV_OFF;
        int*   wis = (int*)(sm + WI_OFF);

        // ---- gi slices (blocks 2..129) ----
        if (wb < 128) {
            int dir = wb >> 6;
            int s = wb & 63;
            int row = dir ? (cL - 1 - s) : s;
            float* xs = sm + XS_OFF;
            const float* Wih = dir ? wb_Wih : wf_Wih;
            const float* bih = dir ? wb_bih : wf_bih;
            if (t < 32) {
                int wid = exec_ids[row];
                ((float4*)xs)[t] = ((const float4*)(emb + (long)wid * cEMB))[t];
            }
            __syncthreads();
            if (t < cG3) {
                const float4* w4 = (const float4*)(Wih + (long)t * cEMB);
                const float4* xx4 = (const float4*)xs;
                float a0 = 0.f, a1 = 0.f;
#pragma unroll
                for (int k = 0; k < 32; k += 2) {
                    float4 w = w4[k];      float4 x = xx4[k];
                    a0 += w.x * x.x + w.y * x.y + w.z * x.z + w.w * x.w;
                    float4 w2 = w4[k + 1]; float4 x2 = xx4[k + 1];
                    a1 += w2.x * x2.x + w2.y * x2.y + w2.z * x2.z + w2.w * x2.w;
                }
                g_gi[dir][s][t] = a0 + a1 + bih[t];
            }
            __threadfence();
            __syncthreads();
            if (t == 0) atomicAdd(&g_gi_done, 1);
        }

        if (wb == 0 && t == 1) {
            out[OUT_HS + 0] = hs[0];
            out[OUT_HS + 1] = hs[1];
            out[OUT_HS + 2] = hs[2];
            out[OUT_HS + (long)cN * cHID - 1] = hs[(long)cN * cHID - 1];
        }

        if (lane < cK) { wv[warp * cK + lane] = -1e30f; wis[warp * cK + lane] = 0; }
        __syncthreads();

        // ---- phase 1: hs copy via cp.async double-buffer pipeline ----
        {
            const float4* s4 = (const float4*)hs;
            float4* d4 = (float4*)(out + OUT_HS + 3);
            unsigned int sbase = (unsigned int)__cvta_generic_to_shared(sm);

            long g = wb;
            int cur = 0;
            if (g < NG1) {
                long base = g * 4096L;
#pragma unroll
                for (int k = 0; k < 4; ++k) {
                    long idx = base + k * 1024 + t;
                    if (idx < SHS_TOT)
                        CPA16(sbase + (unsigned int)(k * 1024 + t) * 16u,
                              (const void*)(s4 + idx));
                }
                if (t == 0 && base + 4096 < SHS_TOT)
                    CPA16(sbase + 4096u * 16u, (const void*)(s4 + base + 4096));
            }
            CPA_COMMIT();

            while (g < NG1) {
                long gn = g + NWRK;
                if (gn < NG1) {
                    long base = gn * 4096L;
                    unsigned int sb = sbase
                        + (unsigned int)((cur ^ 1) * BUFSTRIDE) * 4u;
#pragma unroll
                    for (int k = 0; k < 4; ++k) {
                        long idx = base + k * 1024 + t;
                        if (idx < SHS_TOT)
                            CPA16(sb + (unsigned int)(k * 1024 + t) * 16u,
                                  (const void*)(s4 + idx));
                    }
                    if (t == 0 && base + 4096 < SHS_TOT)
                        CPA16(sb + 4096u * 16u, (const void*)(s4 + base + 4096));
                }
                CPA_COMMIT();
                CPA_WAIT1();
                __syncthreads();

                {
                    const float4* b4 = (const float4*)(sm + cur * BUFSTRIDE);
                    const float*  bf = sm + cur * BUFSTRIDE;
                    long nbase = g * 4096L;
#pragma unroll
                    for (int k = 0; k < 4; ++k) {
                        int loc = k * 1024 + t;
                        long n = nbase + loc;
                        float4 v = b4[loc + 1];
                        float w = __shfl_up_sync(FULLM, v.w, 1);
                        if (lane == 0) w = bf[loc * 4 + 3];
                        if (n < QHS)
                            __stcs(d4 + n, make_float4(w, v.x, v.y, v.z));
                    }
                }
                __syncthreads();
                cur ^= 1;
                g = gn;
            }
            CPA_WAIT0();
            __syncthreads();
        }

        // ---- phase 2: excs via cp.async, granule = 32 rows (warp/row) ----
        const int wbase = warp * cK;
        float t9 = -1e30f;
        bool have = false;
        float4 ea, eb;
        int nd = 0;
        int list[NDL];

#define TOPK_INS(PP, RR)                                                      \
        if ((PP) > t9) {                                                      \
            if (lane == 0) {                                                  \
                int pos = cK - 1;                                             \
                while (pos > 0 && wv[wbase + pos - 1] < (PP)) {               \
                    wv[wbase + pos] = wv[wbase + pos - 1];                    \
                    wis[wbase + pos] = wis[wbase + pos - 1];                  \
                    --pos;                                                    \
                }                                                             \
                wv[wbase + pos] = (PP);                                       \
                wis[wbase + pos] = (RR);                                      \
            }                                                                 \
            __syncwarp();                                                     \
            t9 = wv[wbase + cK - 1];                                          \
        }

        {
            unsigned int sbase = (unsigned int)__cvta_generic_to_shared(sm);
            long g = wb;
            int cur = 0;
            if (g < NG2) {
                const float4* src = (const float4*)(excs + g * 8192L);
                CPA16(sbase + (unsigned int)t * 16u, (const void*)(src + t));
                CPA16(sbase + (unsigned int)(t + 1024) * 16u,
                      (const void*)(src + t + 1024));
            }
            CPA_COMMIT();

            while (g < NG2) {
                long gn = g + NWRK;
                if (gn < NG2) {
                    unsigned int sb = sbase
                        + (unsigned int)((cur ^ 1) * B2STRIDE) * 4u;
                    const float4* src = (const float4*)(excs + gn * 8192L);
                    CPA16(sb + (unsigned int)t * 16u, (const void*)(src + t));
                    CPA16(sb + (unsigned int)(t + 1024) * 16u,
                          (const void*)(src + t + 1024));
                }
                CPA_COMMIT();
                CPA_WAIT1();
                if (t == 0) {
                    int rdy = (*(volatile int*)&g_gru_done == 2);
                    if (!rdy && nd >= NDL) {
                        while (*(volatile int*)&g_gru_done < 2) __nanosleep(64);
                        rdy = 1;
                    }
                    sh_ready = rdy;
                }
                __syncthreads();
                if (!have && sh_ready) {
                    __threadfence();
                    ea = ((const float4*)g_exc)[lane];
                    eb = ((const float4*)g_exc)[32 + lane];
                    have = true;
                }

                // process row r = g*32 + warp from buffer cur
                {
                    const float4* rp =
                        (const float4*)(sm + cur * B2STRIDE + warp * 256);
                    float4 a  = rp[lane];
                    float4 b2 = rp[32 + lane];
                    float4 a1 = rp[lane + 1];
                    float4 b1 = make_float4(0.f, 0.f, 0.f, 0.f);
                    if (lane < 31) b1 = rp[33 + lane];
                    long r = g * 32 + warp;
                    float* drow = out + OUT_EXCS + r * cEXC;
                    float4* d4r = (float4*)(drow + 3);
                    if (lane == 0) {
                        drow[0] = a.x; drow[1] = a.y; drow[2] = a.z;
                    }
                    __stcs(d4r + lane, make_float4(a.w, a1.x, a1.y, a1.z));
                    if (lane < 31)
                        __stcs(d4r + 32 + lane,
                               make_float4(b2.w, b1.x, b1.y, b1.z));
                    else drow[255] = b2.w;

                    if (have) {
                        float p = a.x * ea.x + a.y * ea.y + a.z * ea.z
                                + a.w * ea.w + b2.x * eb.x + b2.y * eb.y
                                + b2.z * eb.z + b2.w * eb.w;
#pragma unroll
                        for (int o = 16; o; o >>= 1)
                            p += __shfl_xor_sync(FULLM, p, o);
                        TOPK_INS(p, (int)r);
                    }
                }
                if (!have) list[nd++] = (int)g;
                __syncthreads();
                cur ^= 1;
                g = gn;
            }
            CPA_WAIT0();
        }

        // ---- deferred dots (re-read from global, no stores) ----
        if (nd > 0) {
            if (!have) {
                while (*(volatile int*)&g_gru_done < 2) __nanosleep(64);
                __threadfence();
                ea = ((const float4*)g_exc)[lane];
                eb = ((const float4*)g_exc)[32 + lane];
            }
            for (int i = 0; i < nd; ++i) {
                long r = (long)list[i] * 32 + warp;
                const float4* rp = (const float4*)(excs + r * cEXC);
                float4 a  = rp[lane];
                float4 b2 = rp[32 + lane];
                float p = a.x * ea.x + a.y * ea.y + a.z * ea.z + a.w * ea.w
                        + b2.x * eb.x + b2.y * eb.y + b2.z * eb.z + b2.w * eb.w;
#pragma unroll
                for (int o = 16; o; o >>= 1) p += __shfl_xor_sync(FULLM, p, o);
                TOPK_INS(p, (int)r);
            }
        }
#undef TOPK_INS
        __syncthreads();

        // ---- block merge: warp 0, 10 rounds over 320 entries ----
        if (warp == 0) {
            for (int j = 0; j < cK; ++j) {
                float bv = -3e30f; int bm = 0;
                for (int m = lane; m < 32 * cK; m += 32)
                    if (wv[m] > bv) { bv = wv[m]; bm = m; }
#pragma unroll
                for (int o = 16; o; o >>= 1) {
                    float ov = __shfl_xor_sync(FULLM, bv, o);
                    int   om = __shfl_xor_sync(FULLM, bm, o);
                    if (ov > bv) { bv = ov; bm = om; }
                }
                if (lane == 0) {
                    g_cv[wb * cK + j] = bv;
                    g_ci[wb * cK + j] = wis[bm];
                    wv[bm] = -3e30f;
                }
                __syncwarp();
                __threadfence_block();
            }
        }
        __threadfence();
        __syncthreads();
    }

    // ================= completion ticket =================
    if (t == 0) {
        int v = atomicAdd(&g_ticket, 1);
        is_last = (v == NBLK - 1);
    }
    __syncthreads();
    if (!is_last) return;
    __threadfence();

    // ================= FINAL (last-finishing block) =================
    {
        float* cv   = sm;                   // [0,1460)
        int*   ci   = (int*)(sm + 1472);
        float* topv = sm + 2944;
        float* wgt  = sm + 2960;
        int*   topi = (int*)(sm + 2976);
        float* exc2 = sm + 3008;
        float* h2   = sm + 3264;
        float* attn = sm + 3520;
        float* red  = sm + 3776;            // 512

        __syncthreads();
        for (int i = t; i < NCAND; i += TPB) { cv[i] = g_cv[i]; ci[i] = g_ci[i]; }
        if (t < cEXC) exc2[t] = g_exc[t];
        else if (t < 512) h2[t - 256] = hs[(long)(cN - 1) * cHID + (t - 256)];
        __syncthreads();

        if (warp == 0) {
            for (int j = 0; j < cK; ++j) {
                float bv = -1e30f; int bi = 0;
                for (int i = lane; i < NCAND; i += 32)
                    if (cv[i] > bv) { bv = cv[i]; bi = i; }
#pragma unroll
                for (int o = 16; o; o >>= 1) {
                    float ov = __shfl_xor_sync(FULLM, bv, o);
                    int   oi = __shfl_xor_sync(FULLM, bi, o);
                    if (ov > bv) { bv = ov; bi = oi; }
                }
                if (lane == 0) {
                    topv[j] = bv;
                    topi[j] = ci[bi];
                    cv[bi] = -3e30f;
                }
                __syncwarp();
            }
            if (lane == 0) {
                float mx = topv[0];
                float ssum = 0.f;
                for (int j = 0; j < cK; ++j) {
                    wgt[j] = expf(topv[j] - mx);
                    ssum += wgt[j];
                }
                for (int j = 0; j < cK; ++j) wgt[j] /= ssum;
            }
        }
        __syncthreads();

        if (t < cHID) {
            float a = 0.f;
#pragma unroll
            for (int j = 0; j < cK; ++j)
                a += wgt[j] * hs[(long)topi[j] * cHID + t];
            attn[t] = a;
        }
        __syncthreads();

        if (t < 512) {
            float v = (t < cEXC) ? exc2[t] : attn[t - cEXC];
            red[t] = v * out_W[t];
        }
        __syncthreads();
        for (int sft = 256; sft; sft >>= 1) {
            if (t < sft) red[t] += red[t + sft];
            __syncthreads();
        }
        if (t == 0) out[OUT_PRED] = red[0] + out_b[0];

        if (t < cHID) {
            float rr = sigmoidf_(g_giv[t] + g_ghv[t]);
            float zz = sigmoidf_(g_giv[cHID + t] + g_ghv[cHID + t]);
            float nn = tanhf(g_giv[2 * cHID + t] + rr * g_ghv[2 * cHID + t]);
            float hn = (1.0f - zz) * nn + zz * h2[t];
            out[OUT_HS + (long)cN * cHID + t] = hn;
        }
        if (t < cEXC)
            out[OUT_EXCS + (long)cN * cEXC + t] = exc2[t];

        if (t == 0) {
            g_gru_done = 0;
            g_ticket = 0;
            g_gi_done = 0;
        }
    }
}

// ============================================================
extern "C" void kernel_launch(void* const* d_in, const int* in_sizes, int n_in,
                              void* d_out, int out_size) {
    const int*   exec_ids = (const int*)d_in[0];
    const float* score    = (const float*)d_in[1];
    const float* excs     = (const float*)d_in[2];
    const float* hs       = (const float*)d_in[3];
    const float* emb      = (const float*)d_in[4];
    const float* wf_Wih   = (const float*)d_in[5];
    const float* wf_Whh   = (const float*)d_in[6];
    const float* wf_bih   = (const float*)d_in[7];
    const float* wf_bhh   = (const float*)d_in[8];
    const float* wb_Wih   = (const float*)d_in[9];
    const float* wb_Whh   = (const float*)d_in[10];
    const float* wb_bih   = (const float*)d_in[11];
    const float* wb_bhh   = (const float*)d_in[12];
    const float* s_Wih    = (const float*)d_in[13];
    const float* s_Whh    = (const float*)d_in[14];
    const float* s_bih    = (const float*)d_in[15];
    const float* s_bhh    = (const float*)d_in[16];
    const float* out_W    = (const float*)d_in[17];
    const float* out_b    = (const float*)d_in[18];
    float* out = (float*)d_out;

    const int fused_smem = SM_FLOATS * sizeof(float);  // 204,800 B
    cudaFuncSetAttribute(fused_kernel,
                         cudaFuncAttributeMaxDynamicSharedMemorySize, fused_smem);

    fused_kernel<<<NBLK, TPB, fused_smem>>>(exec_ids, emb, score, excs, hs,
                                            wf_Wih, wf_bih, wb_Wih, wb_bih,
                                            wf_Whh, wf_bhh, wb_Whh, wb_bhh,
                                            s_Wih, s_Whh, s_bih, s_bhh,
                                            out_W, out_b, out);
}

// round 13
// speedup vs baseline: 1.1597x; 1.1597x over previous
#include <cuda_runtime.h>
#include <math.h>
#include <stdint.h>

// ---------------- problem constants ----------------
#define cL    64
#define cEMB  128
#define cH2   128
#define cG3   384      /* 3*H2 */
#define cEXC  256
#define cHID  256
#define cN    200000
#define cK    10

#define OUT_PRED 0L
#define OUT_EXCS 1L
#define OUT_HS   (1L + (long)(cN + 1) * cEXC)   /* 51200257 */

#define NBLK  148                 /* 2 GRU + 146 workers, exactly 1 wave */
#define NWRK  146
#define TPB   1024
#define NW    4672                /* worker warps: 146 blocks x 32 */
#define NCAND 1460
#define FULLM 0xffffffffu

#define QHS   ((long)cN * cHID / 4 - 1)   /* 12,799,999 shifted f4 slots */
#define SHS_TOT (12800000L)               /* total f4 in hs */
#define NG1   3125                /* phase-1 granules of 4096 f4 (64KB) */
#define G_EX  50000               /* excs granules of 4 rows */
#define NDL   12                  /* max deferred granules per warp */

// smem layout (floats):
//   GRU blocks:   [0,49152) W | [49152,49408) hbuf | [49408,49792) gsh
//                 | [49792,49920) gin
//   worker blocks:[0,49200) cp.async staging (3 x 16400) | wv/wis/xs
#define SM_FLOATS 51200
#define BUFSTRIDE 16400           /* p1 staging floats (4097 f4 + pad) */
#define WV_OFF 49920
#define WI_OFF 50240
#define XS_OFF 50560

// ---------------- device scratch (no allocs allowed) ----------------
__device__ float g_gi[2][cL][cG3];
__device__ float g_exc[cEXC];
__device__ float g_cv[NCAND];
__device__ int   g_ci[NCAND];
__device__ float g_giv[3 * cHID];
__device__ float g_ghv[3 * cHID];
__device__ int   g_gi_done;
__device__ int   g_gru_done;
__device__ int   g_ticket;

__device__ __forceinline__ float sigmoidf_(float x) {
    return 1.0f / (1.0f + expf(-x));
}

#define BAR384() asm volatile("bar.sync 1, 384;" ::: "memory")
#define CPA16(saddr, gptr) \
    asm volatile("cp.async.cg.shared.global [%0], [%1], 16;" \
                 :: "r"(saddr), "l"(gptr))
#define CPA_COMMIT() asm volatile("cp.async.commit_group;" ::: "memory")
#define CPA_WAIT2()  asm volatile("cp.async.wait_group 2;" ::: "memory")
#define CPA_WAIT0()  asm volatile("cp.async.wait_group 0;" ::: "memory")

__device__ __forceinline__ void fma_x2(unsigned long long& acc, double w, double h) {
    asm("fma.rn.f32x2 %0, %1, %2, %0;"
        : "+l"(acc)
        : "l"(__double_as_longlong(w)), "l"(__double_as_longlong(h)));
}
__device__ __forceinline__ void unpack_x2(unsigned long long v, float& lo, float& hi) {
    asm("mov.b64 {%0, %1}, %2;" : "=f"(lo), "=f"(hi) : "l"(v));
}

// ============================================================
__global__ void __launch_bounds__(TPB, 1)
fused_kernel(const int* __restrict__ exec_ids,
             const float* __restrict__ emb,
             const float* __restrict__ score,
             const float* __restrict__ excs,
             const float* __restrict__ hs,
             const float* __restrict__ wf_Wih, const float* __restrict__ wf_bih,
             const float* __restrict__ wb_Wih, const float* __restrict__ wb_bih,
             const float* __restrict__ wf_Whh, const float* __restrict__ wf_bhh,
             const float* __restrict__ wb_Whh, const float* __restrict__ wb_bhh,
             const float* __restrict__ s_Wih,  const float* __restrict__ s_Whh,
             const float* __restrict__ s_bih,  const float* __restrict__ s_bhh,
             const float* __restrict__ out_W,  const float* __restrict__ out_b,
             float* __restrict__ out) {
    extern __shared__ float sm[];
    __shared__ int is_last;
    int t = threadIdx.x;
    int lane = t & 31;
    int warp = t >> 5;
    int b = blockIdx.x;

    if (b < 2) {
        // ================= GRU block (dir = b) =================
        if (warp < 12) {
            int dir = b;
            float* Wsh  = sm;
            float* hbuf = sm + cG3 * cH2;
            float* gsh  = hbuf + 256;
            float* gin  = gsh + 384;

            const float* Whh = dir ? wb_Whh : wf_Whh;
            const float* bhh = dir ? wb_bhh : wf_bhh;

            for (int idx = t; idx < cG3 * cH2 / 4; idx += 384) {
                int kk = idx / cG3;
                int tt = idx - kk * cG3;
                ((float4*)Wsh)[idx] = *(const float4*)(Whh + (long)tt * cH2 + kk * 4);
            }
            if (t < cH2) hbuf[t] = 0.0f;
            float bhh_t = bhh[t];
            float hmax = -1e30f;

            if (t == 0) {
                while (*(volatile int*)&g_gi_done < 128) __nanosleep(32);
            }
            BAR384();
            __threadfence();

            float gi_cur = g_gi[dir][0][t];
            const double2* W2 = ((const double2*)Wsh) + t;

            for (int s = 0; s < cL; ++s) {
                float gi_nxt = (s + 1 < cL) ? g_gi[dir][s + 1][t] : 0.0f;
                float* hcur = hbuf + ((s & 1) ? 128 : 0);
                float* hnxt = hbuf + ((s & 1) ? 0 : 128);
                const double2* H2 = (const double2*)hcur;

                unsigned long long aA = 0, aB = 0, aC = 0, aD = 0;
#pragma unroll
                for (int kk = 0; kk < 32; kk += 2) {
                    double2 w0 = W2[(long)kk * cG3];
                    double2 h0 = H2[kk];
                    double2 w1 = W2[(long)(kk + 1) * cG3];
                    double2 h1 = H2[kk + 1];
                    fma_x2(aA, w0.x, h0.x);
                    fma_x2(aB, w0.y, h0.y);
                    fma_x2(aC, w1.x, h1.x);
                    fma_x2(aD, w1.y, h1.y);
                }
                float p0, p1, p2, p3, p4, p5, p6, p7;
                unpack_x2(aA, p0, p1);
                unpack_x2(aB, p2, p3);
                unpack_x2(aC, p4, p5);
                unpack_x2(aD, p6, p7);
                float gh = ((p0 + p1) + (p2 + p3)) + ((p4 + p5) + (p6 + p7)) + bhh_t;

                if (t < 256) {
                    gsh[t] = sigmoidf_(gi_cur + gh);
                } else {
                    gsh[t] = gh;
                    gin[t - 256] = gi_cur;
                }
                BAR384();

                if (t < cH2) {
                    float r = gsh[t];
                    float z = gsh[128 + t];
                    float n = tanhf(gin[t] + r * gsh[256 + t]);
                    float hn = (1.0f - z) * n + z * hcur[t];
                    hnxt[t] = hn;
                    hmax = fmaxf(hmax, hn);
                }
                BAR384();
                gi_cur = gi_nxt;
            }
            if (t < cH2) g_exc[dir * cH2 + t] = hmax;
            __threadfence();
            BAR384();
            if (t == 0) atomicAdd(&g_gru_done, 1);

            if (t == 0) {
                while (*(volatile int*)&g_gru_done < 2) __nanosleep(64);
            }
            BAR384();
            __threadfence();

            // ---- seq-GRU gate preacts: 12 warps x 32 gates ----
            const float4* exc4 = (const float4*)g_exc;
            const float4* hr4  = (const float4*)(hs + (long)(cN - 1) * cHID);
            float4 xa = exc4[lane], xb = exc4[32 + lane];
            float4 ha = hr4[lane],  hb = hr4[32 + lane];
            int off = (score[0] >= 0.5f) ? 0 : 256;
#pragma unroll 4
            for (int jj = 0; jj < 32; ++jj) {
                int g = b * 384 + warp * 32 + jj;
                const float4* wi4 = (const float4*)(s_Wih + (long)g * 512 + off);
                const float4* wh4 = (const float4*)(s_Whh + (long)g * 256);
                float4 a = wi4[lane], bb = wi4[lane + 32];
                float4 c = wh4[lane], d = wh4[lane + 32];
                float giv = a.x * xa.x + a.y * xa.y + a.z * xa.z + a.w * xa.w
                          + bb.x * xb.x + bb.y * xb.y + bb.z * xb.z + bb.w * xb.w;
                float ghv = c.x * ha.x + c.y * ha.y + c.z * ha.z + c.w * ha.w
                          + d.x * hb.x + d.y * hb.y + d.z * hb.z + d.w * hb.w;
#pragma unroll
                for (int o = 16; o; o >>= 1) {
                    giv += __shfl_xor_sync(FULLM, giv, o);
                    ghv += __shfl_xor_sync(FULLM, ghv, o);
                }
                if (lane == 0) {
                    g_giv[g] = giv + s_bih[g];
                    g_ghv[g] = ghv + s_bhh[g];
                }
            }
            __threadfence();
        }
        __syncthreads();
    } else {
        // ================= worker block =================
        int wb = b - 2;
        float* wv  = sm + WV_OFF;
        int*   wis = (int*)(sm + WI_OFF);

        // ---- gi slices (blocks 2..129) ----
        if (wb < 128) {
            int dir = wb >> 6;
            int s = wb & 63;
            int row = dir ? (cL - 1 - s) : s;
            float* xs = sm + XS_OFF;
            const float* Wih = dir ? wb_Wih : wf_Wih;
            const float* bih = dir ? wb_bih : wf_bih;
            if (t < 32) {
                int wid = exec_ids[row];
                ((float4*)xs)[t] = ((const float4*)(emb + (long)wid * cEMB))[t];
            }
            __syncthreads();
            if (t < cG3) {
                const float4* w4 = (const float4*)(Wih + (long)t * cEMB);
                const float4* xx4 = (const float4*)xs;
                float a0 = 0.f, a1 = 0.f;
#pragma unroll
                for (int k = 0; k < 32; k += 2) {
                    float4 w = w4[k];      float4 x = xx4[k];
                    a0 += w.x * x.x + w.y * x.y + w.z * x.z + w.w * x.w;
                    float4 w2 = w4[k + 1]; float4 x2 = xx4[k + 1];
                    a1 += w2.x * x2.x + w2.y * x2.y + w2.z * x2.z + w2.w * x2.w;
                }
                g_gi[dir][s][t] = a0 + a1 + bih[t];
            }
            __threadfence();
            __syncthreads();
            if (t == 0) atomicAdd(&g_gi_done, 1);
        }

        if (wb == 0 && t == 1) {
            out[OUT_HS + 0] = hs[0];
            out[OUT_HS + 1] = hs[1];
            out[OUT_HS + 2] = hs[2];
            out[OUT_HS + (long)cN * cHID - 1] = hs[(long)cN * cHID - 1];
        }

        if (lane < cK) { wv[warp * cK + lane] = -1e30f; wis[warp * cK + lane] = 0; }
        __syncthreads();

        // ---- phase 1: hs copy via cp.async TRIPLE-buffer pipeline ----
        // granule = 4096 f4 output slots; stage 4097 f4 (shift overlap)
        {
            const float4* s4 = (const float4*)hs;
            float4* d4 = (float4*)(out + OUT_HS + 3);
            unsigned int sbase = (unsigned int)__cvta_generic_to_shared(sm);

            // prologue: issue granules wb and wb+NWRK into buffers 0,1
#pragma unroll
            for (int pb = 0; pb < 2; ++pb) {
                long gg = (long)wb + (long)pb * NWRK;
                unsigned int sb = sbase + (unsigned int)(pb * BUFSTRIDE) * 4u;
                if (gg < NG1) {
                    long base = gg * 4096L;
#pragma unroll
                    for (int k = 0; k < 4; ++k) {
                        long idx = base + k * 1024 + t;
                        if (idx < SHS_TOT)
                            CPA16(sb + (unsigned int)(k * 1024 + t) * 16u,
                                  (const void*)(s4 + idx));
                    }
                    if (t == 0 && base + 4096 < SHS_TOT)
                        CPA16(sb + 4096u * 16u, (const void*)(s4 + base + 4096));
                }
                CPA_COMMIT();
            }

            long g = wb;
            int cur = 0;
            while (g < NG1) {
                long gp = g + 2L * NWRK;
                {
                    int nxt = cur + 2; if (nxt >= 3) nxt -= 3;
                    unsigned int sb = sbase + (unsigned int)(nxt * BUFSTRIDE) * 4u;
                    if (gp < NG1) {
                        long base = gp * 4096L;
#pragma unroll
                        for (int k = 0; k < 4; ++k) {
                            long idx = base + k * 1024 + t;
                            if (idx < SHS_TOT)
                                CPA16(sb + (unsigned int)(k * 1024 + t) * 16u,
                                      (const void*)(s4 + idx));
                        }
                        if (t == 0 && base + 4096 < SHS_TOT)
                            CPA16(sb + 4096u * 16u,
                                  (const void*)(s4 + base + 4096));
                    }
                }
                CPA_COMMIT();
                CPA_WAIT2();
                __syncthreads();

                // process buffer cur -> output granule g
                {
                    const float4* b4 = (const float4*)(sm + cur * BUFSTRIDE);
                    const float*  bf = sm + cur * BUFSTRIDE;
                    long nbase = g * 4096L;
#pragma unroll
                    for (int k = 0; k < 4; ++k) {
                        int loc = k * 1024 + t;
                        long n = nbase + loc;
                        float4 v = b4[loc + 1];
                        float w = __shfl_up_sync(FULLM, v.w, 1);
                        if (lane == 0) w = bf[loc * 4 + 3];
                        if (n < QHS)
                            __stcs(d4 + n, make_float4(w, v.x, v.y, v.z));
                    }
                }
                __syncthreads();
                cur = cur + 1; if (cur >= 3) cur -= 3;
                g += NWRK;
            }
            CPA_WAIT0();
            __syncthreads();
        }

        // ---- phase 2: excs copy (+fused dot when exc ready), direct LDG ----
        const int gw = wb * 32 + warp;
        const int wbase = warp * cK;
        float t9 = -1e30f;
        bool have = false;
        float4 ea, eb;
        int nd = 0;
        int list[NDL];

#define TOPK_INS(PP, RR)                                                      \
        if ((PP) > t9) {                                                      \
            if (lane == 0) {                                                  \
                int pos = cK - 1;                                             \
                while (pos > 0 && wv[wbase + pos - 1] < (PP)) {               \
                    wv[wbase + pos] = wv[wbase + pos - 1];                    \
                    wis[wbase + pos] = wis[wbase + pos - 1];                  \
                    --pos;                                                    \
                }                                                             \
                wv[wbase + pos] = (PP);                                       \
                wis[wbase + pos] = (RR);                                      \
            }                                                                 \
            __syncwarp();                                                     \
            t9 = wv[wbase + cK - 1];                                          \
        }

#define ROW_COPY(RR, DODOT)                                                   \
        {                                                                     \
            const float4* rp = (const float4*)(excs + (long)(RR) * cEXC);     \
            float4 a  = rp[lane];                                             \
            float4 b2 = rp[32 + lane];                                        \
            float4 a1 = rp[lane + 1];                                         \
            float4 b1 = make_float4(0.f, 0.f, 0.f, 0.f);                      \
            if (lane < 31) b1 = rp[33 + lane];                                \
            float* drow = out + OUT_EXCS + (long)(RR) * cEXC;                 \
            float4* d4r = (float4*)(drow + 3);                                \
            if (lane == 0) { drow[0] = a.x; drow[1] = a.y; drow[2] = a.z; }   \
            __stcs(d4r + lane, make_float4(a.w, a1.x, a1.y, a1.z));           \
            if (lane < 31) __stcs(d4r + 32 + lane,                            \
                                  make_float4(b2.w, b1.x, b1.y, b1.z));       \
            else drow[255] = b2.w;                                            \
            if (DODOT) {                                                      \
                float p = a.x * ea.x + a.y * ea.y + a.z * ea.z + a.w * ea.w   \
                        + b2.x * eb.x + b2.y * eb.y + b2.z * eb.z             \
                        + b2.w * eb.w;                                        \
                _Pragma("unroll")                                             \
                for (int o = 16; o; o >>= 1)                                  \
                    p += __shfl_xor_sync(FULLM, p, o);                        \
                TOPK_INS(p, (RR));                                            \
            }                                                                 \
        }

        for (int j = gw; j < G_EX; j += NW) {
            if (!have && *(volatile int*)&g_gru_done == 2) {
                __threadfence();
                ea = ((const float4*)g_exc)[lane];
                eb = ((const float4*)g_exc)[32 + lane];
                have = true;
            }
            int r0 = j * 4;
            if (have) {
                ROW_COPY(r0 + 0, 1);
                ROW_COPY(r0 + 1, 1);
                ROW_COPY(r0 + 2, 1);
                ROW_COPY(r0 + 3, 1);
            } else {
                ROW_COPY(r0 + 0, 0);
                ROW_COPY(r0 + 1, 0);
                ROW_COPY(r0 + 2, 0);
                ROW_COPY(r0 + 3, 0);
                if (nd < NDL) list[nd] = j;
                ++nd;
            }
        }

        // ---- deferred dots (re-read, no stores) ----
        if (nd > 0) {
            if (!have) {
                while (*(volatile int*)&g_gru_done < 2) __nanosleep(64);
                __threadfence();
                ea = ((const float4*)g_exc)[lane];
                eb = ((const float4*)g_exc)[32 + lane];
            }
            int nn = nd < NDL ? nd : NDL;
            for (int i = 0; i < nn; ++i) {
                int r0 = list[i] * 4;
#pragma unroll
                for (int rr = 0; rr < 4; ++rr) {
                    const float4* rp = (const float4*)(excs + (long)(r0 + rr) * cEXC);
                    float4 a  = rp[lane];
                    float4 b2 = rp[32 + lane];
                    float p = a.x * ea.x + a.y * ea.y + a.z * ea.z + a.w * ea.w
                            + b2.x * eb.x + b2.y * eb.y + b2.z * eb.z + b2.w * eb.w;
#pragma unroll
                    for (int o = 16; o; o >>= 1) p += __shfl_xor_sync(FULLM, p, o);
                    TOPK_INS(p, r0 + rr);
                }
            }
        }
#undef ROW_COPY
#undef TOPK_INS
        __syncthreads();

        // ---- block merge: warp 0, 10 rounds over 320 entries ----
        if (warp == 0) {
            for (int j = 0; j < cK; ++j) {
                float bv = -3e30f; int bm = 0;
                for (int m = lane; m < 32 * cK; m += 32)
                    if (wv[m] > bv) { bv = wv[m]; bm = m; }
#pragma unroll
                for (int o = 16; o; o >>= 1) {
                    float ov = __shfl_xor_sync(FULLM, bv, o);
                    int   om = __shfl_xor_sync(FULLM, bm, o);
                    if (ov > bv) { bv = ov; bm = om; }
                }
                if (lane == 0) {
                    g_cv[wb * cK + j] = bv;
                    g_ci[wb * cK + j] = wis[bm];
                    wv[bm] = -3e30f;
                }
                __syncwarp();
                __threadfence_block();
            }
        }
        __threadfence();
        __syncthreads();
    }

    // ================= completion ticket =================
    if (t == 0) {
        int v = atomicAdd(&g_ticket, 1);
        is_last = (v == NBLK - 1);
    }
    __syncthreads();
    if (!is_last) return;
    __threadfence();

    // ================= FINAL (last-finishing block) =================
    {
        float* cv   = sm;                   // [0,1460)
        int*   ci   = (int*)(sm + 1472);
        float* topv = sm + 2944;
        float* wgt  = sm + 2960;
        int*   topi = (int*)(sm + 2976);
        float* exc2 = sm + 3008;
        float* h2   = sm + 3264;
        float* attn = sm + 3520;
        float* red  = sm + 3776;            // 512

        __syncthreads();
        for (int i = t; i < NCAND; i += TPB) { cv[i] = g_cv[i]; ci[i] = g_ci[i]; }
        if (t < cEXC) exc2[t] = g_exc[t];
        else if (t < 512) h2[t - 256] = hs[(long)(cN - 1) * cHID + (t - 256)];
        __syncthreads();

        if (warp == 0) {
            for (int j = 0; j < cK; ++j) {
                float bv = -1e30f; int bi = 0;
                for (int i = lane; i < NCAND; i += 32)
                    if (cv[i] > bv) { bv = cv[i]; bi = i; }
#pragma unroll
                for (int o = 16; o; o >>= 1) {
                    float ov = __shfl_xor_sync(FULLM, bv, o);
                    int   oi = __shfl_xor_sync(FULLM, bi, o);
                    if (ov > bv) { bv = ov; bi = oi; }
                }
                if (lane == 0) {
                    topv[j] = bv;
                    topi[j] = ci[bi];
                    cv[bi] = -3e30f;
                }
                __syncwarp();
            }
            if (lane == 0) {
                float mx = topv[0];
                float ssum = 0.f;
                for (int j = 0; j < cK; ++j) {
                    wgt[j] = expf(topv[j] - mx);
                    ssum += wgt[j];
                }
                for (int j = 0; j < cK; ++j) wgt[j] /= ssum;
            }
        }
        __syncthreads();

        if (t < cHID) {
            float a = 0.f;
#pragma unroll
            for (int j = 0; j < cK; ++j)
                a += wgt[j] * hs[(long)topi[j] * cHID + t];
            attn[t] = a;
        }
        __syncthreads();

        if (t < 512) {
            float v = (t < cEXC) ? exc2[t] : attn[t - cEXC];
            red[t] = v * out_W[t];
        }
        __syncthreads();
        for (int sft = 256; sft; sft >>= 1) {
            if (t < sft) red[t] += red[t + sft];
            __syncthreads();
        }
        if (t == 0) out[OUT_PRED] = red[0] + out_b[0];

        if (t < cHID) {
            float rr = sigmoidf_(g_giv[t] + g_ghv[t]);
            float zz = sigmoidf_(g_giv[cHID + t] + g_ghv[cHID + t]);
            float nn = tanhf(g_giv[2 * cHID + t] + rr * g_ghv[2 * cHID + t]);
            float hn = (1.0f - zz) * nn + zz * h2[t];
            out[OUT_HS + (long)cN * cHID + t] = hn;
        }
        if (t < cEXC)
            out[OUT_EXCS + (long)cN * cEXC + t] = exc2[t];

        if (t == 0) {
            g_gru_done = 0;
            g_ticket = 0;
            g_gi_done = 0;
        }
    }
}

// ============================================================
extern "C" void kernel_launch(void* const* d_in, const int* in_sizes, int n_in,
                              void* d_out, int out_size) {
    const int*   exec_ids = (const int*)d_in[0];
    const float* score    = (const float*)d_in[1];
    const float* excs     = (const float*)d_in[2];
    const float* hs       = (const float*)d_in[3];
    const float* emb      = (const float*)d_in[4];
    const float* wf_Wih   = (const float*)d_in[5];
    const float* wf_Whh   = (const float*)d_in[6];
    const float* wf_bih   = (const float*)d_in[7];
    const float* wf_bhh   = (const float*)d_in[8];
    const float* wb_Wih   = (const float*)d_in[9];
    const float* wb_Whh   = (const float*)d_in[10];
    const float* wb_bih   = (const float*)d_in[11];
    const float* wb_bhh   = (const float*)d_in[12];
    const float* s_Wih    = (const float*)d_in[13];
    const float* s_Whh    = (const float*)d_in[14];
    const float* s_bih    = (const float*)d_in[15];
    const float* s_bhh    = (const float*)d_in[16];
    const float* out_W    = (const float*)d_in[17];
    const float* out_b    = (const float*)d_in[18];
    float* out = (float*)d_out;

    const int fused_smem = SM_FLOATS * sizeof(float);  // 204,800 B
    cudaFuncSetAttribute(fused_kernel,
                         cudaFuncAttributeMaxDynamicSharedMemorySize, fused_smem);

    fused_kernel<<<NBLK, TPB, fused_smem>>>(exec_ids, emb, score, excs, hs,
                                            wf_Wih, wf_bih, wb_Wih, wb_bih,
                                            wf_Whh, wf_bhh, wb_Whh, wb_bhh,
                                            s_Wih, s_Whh, s_bih, s_bhh,
                                            out_W, out_b, out);
}